// round 13
// baseline (speedup 1.0000x reference)
#include <cuda_runtime.h>
#include <math_constants.h>

#define NP    16384
#define GRIDD 32
#define NCELL (GRIDD * GRIDD * GRIDD)   // 32768
#define ORG   (-4.5f)
#define WID   (9.0f / GRIDD)            // 0.28125
#define INVW  (GRIDD / 9.0f)
#define FULLM 0xffffffffu
#define FXS   268435456.0f              // 2^28 fixed point
#define CAP   64
#define OVCAP 1024
#define NBLK  592
#define TPB   256
#define CHUNK 4

// ---------------- device scratch (zero-init; kernel self-resets for replays) ----
__device__ int    g_count[2][NCELL];
__device__ float4 g_bkt[2][NCELL * CAP];   // (x,y,z,|p|^2)
__device__ float4 g_dense[2][NP];          // (x,y,z,|p|^2)
__device__ int    g_ovf_n[2];
__device__ float4 g_ovf[2][OVCAP];
__device__ unsigned long long g_dist_acc;
__device__ unsigned long long g_col_acc;
__device__ unsigned g_bar_cnt;
__device__ unsigned g_bar_gen;             // monotone across replays
__device__ unsigned g_cursor;              // work-stealing cursor (reset per run)

__device__ __forceinline__ int clampi(int v, int lo, int hi) {
    return v < lo ? lo : (v > hi ? hi : v);
}
__device__ __forceinline__ void cell_of(float x, float y, float z,
                                        int& cx, int& cy, int& cz) {
    cx = clampi((int)floorf((x - ORG) * INVW), 0, GRIDD - 1);
    cy = clampi((int)floorf((y - ORG) * INVW), 0, GRIDD - 1);
    cz = clampi((int)floorf((z - ORG) * INVW), 0, GRIDD - 1);
}
__device__ __forceinline__ float warp_min(float v) {
#pragma unroll
    for (int s = 16; s > 0; s >>= 1)
        v = fminf(v, __shfl_xor_sync(FULLM, v, s));
    return v;
}

__device__ __forceinline__ void grid_barrier() {
    __syncthreads();
    if (threadIdx.x == 0) {
        volatile unsigned* gen_p = &g_bar_gen;
        unsigned gen = *gen_p;
        __threadfence();
        if (atomicAdd(&g_bar_cnt, 1u) == NBLK - 1) {
            g_bar_cnt = 0;
            __threadfence();
            *gen_p = gen + 1;
        } else {
            while (*gen_p == gen) __nanosleep(64);
        }
        __threadfence();
    }
    __syncthreads();
}

// cooperative brute force (t-form): returns warp-reduced min of g2 - 2 q.g
__device__ __forceinline__ float brute_one_t(const float4* __restrict__ dns,
                                             float mx, float my, float mz, int lane) {
    float b0 = CUDART_INF_F, b1 = CUDART_INF_F, b2 = CUDART_INF_F, b3 = CUDART_INF_F;
#pragma unroll 8
    for (int p = lane; p < NP; p += 128) {
        float4 ga = dns[p];
        float4 gb = dns[p + 32];
        float4 gc = dns[p + 64];
        float4 gd = dns[p + 96];
        b0 = fminf(b0, fmaf(mx, ga.x, fmaf(my, ga.y, fmaf(mz, ga.z, ga.w))));
        b1 = fminf(b1, fmaf(mx, gb.x, fmaf(my, gb.y, fmaf(mz, gb.z, gb.w))));
        b2 = fminf(b2, fmaf(mx, gc.x, fmaf(my, gc.y, fmaf(mz, gc.z, gc.w))));
        b3 = fminf(b3, fmaf(mx, gd.x, fmaf(my, gd.y, fmaf(mz, gd.z, gd.w))));
    }
    return warp_min(fminf(fminf(b0, b1), fminf(b2, b3)));
}

// scan the (2k+1)^3 box: warp-uniform broadcast LDG per candidate, t-form math
__device__ void scan_box_bcast(
    const int* __restrict__ cnts, const float4* __restrict__ bkt,
    int cx, int cy, int cz, int k, int lane, bool dual,
    float m1x, float m1y, float m1z,
    float m2x, float m2y, float m2z,
    float& t1, float& t2)
{
    const int W = 2 * k + 1, ncell = W * W * W;
    for (int cb = 0; cb < ncell; cb += 32) {
        int cc = cb + lane;
        int s = 0, c = 0;
        if (cc < ncell) {
            int dz = cc / (W * W), rem = cc - dz * W * W;
            int dy = rem / W, dx = rem - dy * W;
            int zc = cz + dz - k, yc = cy + dy - k, xc = cx + dx - k;
            if ((unsigned)zc < GRIDD && (unsigned)yc < GRIDD && (unsigned)xc < GRIDD) {
                int cel = (zc * GRIDD + yc) * GRIDD + xc;
                c = min(cnts[cel], CAP);
                s = cel * CAP;
            }
        }
        unsigned nz = __ballot_sync(FULLM, c > 0);
        while (nz) {
            int r = __ffs(nz) - 1;
            nz &= nz - 1;
            int bs = __shfl_sync(FULLM, s, r);
            int ct = __shfl_sync(FULLM, c, r);
            if (!dual) {
#pragma unroll 4
                for (int j = 0; j < ct; j++) {
                    float4 g = bkt[bs + j];     // uniform addr -> broadcast LDG
                    t1 = fminf(t1, fmaf(m1x, g.x, fmaf(m1y, g.y, fmaf(m1z, g.z, g.w))));
                }
            } else {
#pragma unroll 2
                for (int j = 0; j < ct; j++) {
                    float4 g = bkt[bs + j];
                    t1 = fminf(t1, fmaf(m1x, g.x, fmaf(m1y, g.y, fmaf(m1z, g.z, g.w))));
                    t2 = fminf(t2, fmaf(m2x, g.x, fmaf(m2y, g.y, fmaf(m2z, g.z, g.w))));
                }
            }
        }
    }
}

// process one cell's queries against its neighborhood
__device__ void process_cell(int cl, int cell, int cnt, int lane) {
    const int sdb = cl ^ 1;
    const int nq = min(cnt, CAP);
    const bool dual = (nq > 32);
    const int cx = cell & 31, cy = (cell >> 5) & 31, cz = cell >> 10;

    const bool a1 = lane < nq;
    const bool a2 = lane + 32 < nq;
    float4 q1 = make_float4(0.f, 0.f, 0.f, 0.f), q2 = q1;
    if (a1) q1 = g_bkt[cl][cell * CAP + lane];
    if (a2) q2 = g_bkt[cl][cell * CAP + lane + 32];
    const bool qok1 = !a1 || (q1.x > ORG && q1.x < ORG + 9.0f &&
                              q1.y > ORG && q1.y < ORG + 9.0f &&
                              q1.z > ORG && q1.z < ORG + 9.0f);
    const bool qok2 = !a2 || (q2.x > ORG && q2.x < ORG + 9.0f &&
                              q2.y > ORG && q2.y < ORG + 9.0f &&
                              q2.z > ORG && q2.z < ORG + 9.0f);

    const float m1x = -2.0f * q1.x, m1y = -2.0f * q1.y, m1z = -2.0f * q1.z;
    const float m2x = -2.0f * q2.x, m2y = -2.0f * q2.y, m2z = -2.0f * q2.z;

    const int*    __restrict__ cnts = g_count[sdb];
    const float4* __restrict__ bkt  = g_bkt[sdb];

    float t1 = CUDART_INF_F, t2 = CUDART_INF_F;

    // opposite-cloud overflow points (normally none) — broadcast loop
    int novf = min(g_ovf_n[sdb], OVCAP);
    for (int j = 0; j < novf; j++) {
        float4 g = g_ovf[sdb][j];
        t1 = fminf(t1, fmaf(m1x, g.x, fmaf(m1y, g.y, fmaf(m1z, g.z, g.w))));
        if (dual)
            t2 = fminf(t2, fmaf(m2x, g.x, fmaf(m2y, g.y, fmaf(m2z, g.z, g.w))));
    }

    // phase A: 3x3x3
    scan_box_bcast(cnts, bkt, cx, cy, cz, 1, lane, dual,
                   m1x, m1y, m1z, m2x, m2y, m2z, t1, t2);

    float best1 = q1.w + t1;       // true squared distance (may be ~-eps)
    float best2 = q2.w + t2;
    const float B1 = WID * WID;
    unsigned bad = __ballot_sync(FULLM,
        (a1 && (!qok1 || best1 > B1)) || (a2 && (!qok2 || best2 > B1)));

    if (bad) {
        // phase B: 5x5x5 (min accumulates; rescan of inner cells is harmless)
        scan_box_bcast(cnts, bkt, cx, cy, cz, 2, lane, dual,
                       m1x, m1y, m1z, m2x, m2y, m2z, t1, t2);
        best1 = q1.w + t1;
        best2 = q2.w + t2;

        // phase C: per-query cooperative brute (rarer)
        const float B2 = 4.0f * WID * WID;
        const float4* __restrict__ dns = g_dense[sdb];
        unsigned f1 = __ballot_sync(FULLM, a1 && (!qok1 || best1 > B2));
        while (f1) {
            int r = __ffs(f1) - 1;
            f1 &= f1 - 1;
            float fx = __shfl_sync(FULLM, m1x, r);
            float fy = __shfl_sync(FULLM, m1y, r);
            float fz = __shfl_sync(FULLM, m1z, r);
            float nt = brute_one_t(dns, fx, fy, fz, lane);
            if (lane == r) best1 = q1.w + nt;
        }
        unsigned f2 = __ballot_sync(FULLM, a2 && (!qok2 || best2 > B2));
        while (f2) {
            int r = __ffs(f2) - 1;
            f2 &= f2 - 1;
            float fx = __shfl_sync(FULLM, m2x, r);
            float fy = __shfl_sync(FULLM, m2y, r);
            float fz = __shfl_sync(FULLM, m2z, r);
            float nt = brute_one_t(dns, fx, fy, fz, lane);
            if (lane == r) best2 = q2.w + nt;
        }
    }

    long long di = 0;
    if (a1) di += (long long)llrintf(sqrtf(fmaxf(best1, 0.0f)) * FXS);
    if (a2) di += (long long)llrintf(sqrtf(fmaxf(best2, 0.0f)) * FXS);
#pragma unroll
    for (int s = 16; s > 0; s >>= 1)
        di += __shfl_xor_sync(FULLM, di, s);
    if (lane == 0 && di != 0)
        atomicAdd(&g_dist_acc, (unsigned long long)di);
}

// ---------------- the ONE fused kernel ----------------
__global__ __launch_bounds__(TPB, 4)
void fused_kernel(const float* __restrict__ pred, const float* __restrict__ gt,
                  float* __restrict__ out) {
    const int gtid = blockIdx.x * TPB + threadIdx.x;
    const int lane = threadIdx.x & 31;
    const int gwarp = gtid >> 5;

    // ======== phase 1: bin (with |p|^2 in w) + dense copy + color loss ========
    if (gtid < 2 * NP) {
        int cloud = gtid >> 14;
        int idx = gtid & (NP - 1);
        const float* r = (cloud ? gt : pred) + (size_t)idx * 6;
        float x = r[0], y = r[1], z = r[2];
        float g2 = fmaf(x, x, fmaf(y, y, z * z));
        float4 pt = make_float4(x, y, z, g2);
        g_dense[cloud][idx] = pt;

        int cx, cy, cz;
        cell_of(x, y, z, cx, cy, cz);
        int cell = (cz * GRIDD + cy) * GRIDD + cx;
        int slot = atomicAdd(&g_count[cloud][cell], 1);
        if (slot < CAP) {
            g_bkt[cloud][cell * CAP + slot] = pt;
        } else {
            int o = atomicAdd(&g_ovf_n[cloud], 1);
            if (o < OVCAP) g_ovf[cloud][o] = pt;
        }

        long long ci = 0;
        if (cloud == 0) {
            const float* pc = pred + (size_t)idx * 6;
            const float* gc = gt + (size_t)idx * 6;
            float col = fabsf(pc[3] - gc[3]) + fabsf(pc[4] - gc[4]) + fabsf(pc[5] - gc[5]);
            ci = llrintf(col * FXS);
        }
#pragma unroll
        for (int s = 16; s > 0; s >>= 1)
            ci += __shfl_xor_sync(FULLM, ci, s);
        if (lane == 0 && ci != 0)
            atomicAdd(&g_col_acc, (unsigned long long)ci);
    }

    grid_barrier();

    // ======== phase 2: NN, dynamic work stealing (CHUNK cells per steal) ========
    {
        const int* __restrict__ call = (const int*)g_count;
        for (;;) {
            unsigned base = 0;
            if (lane == 0) base = atomicAdd(&g_cursor, CHUNK);
            base = __shfl_sync(FULLM, base, 0);
            if (base >= 2 * NCELL) break;
            int cnt = 0;
            if (lane < CHUNK) cnt = call[base + lane];
            unsigned act = __ballot_sync(FULLM, lane < CHUNK && cnt > 0);
            while (act) {
                int k = __ffs(act) - 1;
                act &= act - 1;
                int item = base + k;
                int c = __shfl_sync(FULLM, cnt, k);
                process_cell(item >> 15, item & (NCELL - 1), c, lane);
            }
        }
        // overflow queries (normally none)
        if (gwarp < 2) {
            int cl = gwarp;
            int n = min(g_ovf_n[cl], OVCAP);
            for (int o = 0; o < n; o++) {
                float4 q = g_ovf[cl][o];
                float nt = brute_one_t(g_dense[cl ^ 1],
                                       -2.0f * q.x, -2.0f * q.y, -2.0f * q.z, lane);
                if (lane == 0)
                    atomicAdd(&g_dist_acc, (unsigned long long)(long long)
                              llrintf(sqrtf(fmaxf(q.w + nt, 0.0f)) * FXS));
            }
        }
    }

    grid_barrier();

    // ======== phase 3: combine + reset for next replay ========
    if (gtid == 0) {
        double dist = (double)(long long)g_dist_acc * (1.0 / 268435456.0);
        double col  = (double)(long long)g_col_acc  * (1.0 / 268435456.0);
        out[0] = (float)(dist / (double)NP + 0.1 * col / (double)(NP * 3));
        g_dist_acc = 0;
        g_col_acc  = 0;
    }
    if (gtid == 32) { g_ovf_n[0] = 0; g_ovf_n[1] = 0; }
    if (gtid == 64) g_cursor = 0;
    if (gtid < 2 * NCELL) ((int*)g_count)[gtid] = 0;
}

extern "C" void kernel_launch(void* const* d_in, const int* in_sizes, int n_in,
                              void* d_out, int out_size) {
    const float* pred = (const float*)d_in[0];
    const float* gt   = (const float*)d_in[1];
    float* out        = (float*)d_out;
    (void)in_sizes; (void)n_in; (void)out_size;

    fused_kernel<<<NBLK, TPB>>>(pred, gt, out);
}

// round 14
// speedup vs baseline: 1.7631x; 1.7631x over previous
#include <cuda_runtime.h>
#include <math_constants.h>

#define NP    16384
#define GRIDD 32
#define NCELL (GRIDD * GRIDD * GRIDD)   // 32768
#define ORG   (-4.5f)
#define WID   (9.0f / GRIDD)            // 0.28125
#define INVW  (GRIDD / 9.0f)
#define FULLM 0xffffffffu
#define FXS   268435456.0f              // 2^28 fixed point
#define CAP   64
#define OVCAP 1024

// ---------------- device scratch (zero-init; finish_kernel resets for replays) ----
__device__ int    g_count[2][NCELL];
__device__ float4 g_bkt[2][NCELL * CAP];   // (x,y,z,|p|^2)
__device__ float4 g_dense[2][NP];          // (x,y,z,|p|^2)
__device__ int    g_ovf_n[2];
__device__ float4 g_ovf[2][OVCAP];
__device__ unsigned long long g_dist_acc;
__device__ unsigned long long g_col_acc;

__device__ __forceinline__ int clampi(int v, int lo, int hi) {
    return v < lo ? lo : (v > hi ? hi : v);
}
__device__ __forceinline__ void cell_of(float x, float y, float z,
                                        int& cx, int& cy, int& cz) {
    cx = clampi((int)floorf((x - ORG) * INVW), 0, GRIDD - 1);
    cy = clampi((int)floorf((y - ORG) * INVW), 0, GRIDD - 1);
    cz = clampi((int)floorf((z - ORG) * INVW), 0, GRIDD - 1);
}
__device__ __forceinline__ float warp_min(float v) {
#pragma unroll
    for (int s = 16; s > 0; s >>= 1)
        v = fminf(v, __shfl_xor_sync(FULLM, v, s));
    return v;
}
__device__ __forceinline__ float sel8(const float t[8], int u) {
    float v = t[0];
    if (u == 1) v = t[1];
    if (u == 2) v = t[2];
    if (u == 3) v = t[3];
    if (u == 4) v = t[4];
    if (u == 5) v = t[5];
    if (u == 6) v = t[6];
    if (u == 7) v = t[7];
    return v;
}

// cooperative brute force (t-form): warp-reduced min of g2 - 2 q.g over all NP
__device__ __forceinline__ float brute_one_t(const float4* __restrict__ dns,
                                             float mx, float my, float mz, int lane) {
    float b0 = CUDART_INF_F, b1 = CUDART_INF_F, b2 = CUDART_INF_F, b3 = CUDART_INF_F;
#pragma unroll 8
    for (int p = lane; p < NP; p += 128) {
        float4 ga = dns[p];
        float4 gb = dns[p + 32];
        float4 gc = dns[p + 64];
        float4 gd = dns[p + 96];
        b0 = fminf(b0, fmaf(mx, ga.x, fmaf(my, ga.y, fmaf(mz, ga.z, ga.w))));
        b1 = fminf(b1, fmaf(mx, gb.x, fmaf(my, gb.y, fmaf(mz, gb.z, gb.w))));
        b2 = fminf(b2, fmaf(mx, gc.x, fmaf(my, gc.y, fmaf(mz, gc.z, gc.w))));
        b3 = fminf(b3, fmaf(mx, gd.x, fmaf(my, gd.y, fmaf(mz, gd.z, gd.w))));
    }
    return warp_min(fminf(fminf(b0, b1), fminf(b2, b3)));
}

// ---------------- node 1: bin (|p|^2 in w) + dense copy + color loss ----------------
__global__ __launch_bounds__(256)
void bin_kernel(const float* __restrict__ pred, const float* __restrict__ gt) {
    int i = blockIdx.x * blockDim.x + threadIdx.x;   // [0, 2*NP)
    int lane = threadIdx.x & 31;
    int cloud = i >> 14;
    int idx = i & (NP - 1);
    const float* r = (cloud ? gt : pred) + (size_t)idx * 6;
    float x = r[0], y = r[1], z = r[2];
    float g2 = fmaf(x, x, fmaf(y, y, z * z));
    float4 pt = make_float4(x, y, z, g2);
    g_dense[cloud][idx] = pt;

    int cx, cy, cz;
    cell_of(x, y, z, cx, cy, cz);
    int cell = (cz * GRIDD + cy) * GRIDD + cx;
    int slot = atomicAdd(&g_count[cloud][cell], 1);
    if (slot < CAP) {
        g_bkt[cloud][cell * CAP + slot] = pt;
    } else {
        int o = atomicAdd(&g_ovf_n[cloud], 1);
        if (o < OVCAP) g_ovf[cloud][o] = pt;
    }

    long long ci = 0;
    if (cloud == 0) {
        const float* pc = pred + (size_t)idx * 6;
        const float* gc = gt + (size_t)idx * 6;
        float col = fabsf(pc[3] - gc[3]) + fabsf(pc[4] - gc[4]) + fabsf(pc[5] - gc[5]);
        ci = llrintf(col * FXS);
    }
#pragma unroll
    for (int s = 16; s > 0; s >>= 1)
        ci += __shfl_xor_sync(FULLM, ci, s);
    if (lane == 0 && ci != 0)
        atomicAdd(&g_col_acc, (unsigned long long)ci);
}

// scan the (2K+1)^3 neighborhood: candidates LANE-PARALLEL, queries broadcast
// in groups of 8; per-lane t-accumulators, one warp-reduce per 8-query pass.
__device__ void scan_nbhd(const int* __restrict__ cnts, const float4* __restrict__ bkt,
                          int cx, int cy, int cz, int K, int lane, int nq,
                          float m1x, float m1y, float m1z,
                          float m2x, float m2y, float m2z,
                          float& bt1, float& bt2)
{
    const int W = 2 * K + 1, ncell = W * W * W;
    for (int qb = 0; qb < nq; qb += 8) {
        // broadcast 8 queries' -2q (padded queries -> 0 => t = g2, unused)
        float ax[8], ay[8], az[8];
#pragma unroll
        for (int u = 0; u < 8; u++) {
            int j = qb + u;                       // warp-uniform
            float sx, sy, sz;
            if ((j & 32) == 0) { sx = m1x; sy = m1y; sz = m1z; }
            else               { sx = m2x; sy = m2y; sz = m2z; }
            float vx = __shfl_sync(FULLM, sx, j & 31);
            float vy = __shfl_sync(FULLM, sy, j & 31);
            float vz = __shfl_sync(FULLM, sz, j & 31);
            bool on = (j < nq);
            ax[u] = on ? vx : 0.f;
            ay[u] = on ? vy : 0.f;
            az[u] = on ? vz : 0.f;
        }
        float t[8];
#pragma unroll
        for (int u = 0; u < 8; u++) t[u] = CUDART_INF_F;

        for (int cb = 0; cb < ncell; cb += 32) {
            int cc = cb + lane;
            int c = 0, s = 0;
            if (cc < ncell) {
                int dz = cc / (W * W), rem = cc - dz * W * W;
                int dy = rem / W, dx = rem - dy * W;
                int zc = cz + dz - K, yc = cy + dy - K, xc = cx + dx - K;
                if ((unsigned)zc < GRIDD && (unsigned)yc < GRIDD && (unsigned)xc < GRIDD) {
                    int cel = (zc * GRIDD + yc) * GRIDD + xc;
                    c = min(cnts[cel], CAP);
                    s = cel * CAP;
                }
            }
            unsigned nz = __ballot_sync(FULLM, c > 0);
            while (nz) {
                int r = __ffs(nz) - 1;
                nz &= nz - 1;
                int bs = __shfl_sync(FULLM, s, r);
                int ct = __shfl_sync(FULLM, c, r);
                for (int b = 0; b < ct; b += 32) {
                    float4 g = make_float4(0.f, 0.f, 0.f, CUDART_INF_F);
                    if (b + lane < ct) g = bkt[bs + b + lane];   // lane-parallel LDG.128
#pragma unroll
                    for (int u = 0; u < 8; u++)
                        t[u] = fminf(t[u], fmaf(ax[u], g.x,
                                    fmaf(ay[u], g.y, fmaf(az[u], g.z, g.w))));
                }
            }
        }
        // reduce all 8 accumulators together (latency amortized)
#pragma unroll
        for (int sh = 16; sh > 0; sh >>= 1)
#pragma unroll
            for (int u = 0; u < 8; u++)
                t[u] = fminf(t[u], __shfl_xor_sync(FULLM, t[u], sh));

        int u1 = lane - qb;                  // holder lanes pick their result
        if (u1 >= 0 && u1 < 8) bt1 = fminf(bt1, sel8(t, u1));
        int u2 = lane + 32 - qb;
        if (u2 >= 0 && u2 < 8) bt2 = fminf(bt2, sel8(t, u2));
    }
}

// ---------------- node 2: exact NN, one WARP per cell ----------------
__global__ __launch_bounds__(256)
void query_kernel() {
    const int lane = threadIdx.x & 31;

    if (blockIdx.x == 8192) {                 // overflow queries (normally none)
        int w = threadIdx.x >> 5;
        for (int cl2 = 0; cl2 < 2; cl2++) {
            int n = min(g_ovf_n[cl2], OVCAP);
            for (int o = w; o < n; o += 8) {
                float4 q = g_ovf[cl2][o];
                float nt = brute_one_t(g_dense[cl2 ^ 1],
                                       -2.0f * q.x, -2.0f * q.y, -2.0f * q.z, lane);
                if (lane == 0)
                    atomicAdd(&g_dist_acc, (unsigned long long)(long long)
                              llrintf(sqrtf(fmaxf(q.w + nt, 0.0f)) * FXS));
            }
        }
        return;
    }

    const int gw   = (blockIdx.x * 256 + threadIdx.x) >> 5;  // [0, 65536)
    const int cl   = gw >> 15;
    const int cell = gw & (NCELL - 1);
    const int sdb  = cl ^ 1;

    const int cnt = g_count[cl][cell];
    if (cnt == 0) return;
    const int nq = min(cnt, CAP);
    const int cx = cell & 31, cy = (cell >> 5) & 31, cz = cell >> 10;

    const bool a1 = lane < nq;
    const bool a2 = lane + 32 < nq;
    float4 q1 = make_float4(0.f, 0.f, 0.f, 0.f), q2 = q1;
    if (a1) q1 = g_bkt[cl][cell * CAP + lane];
    if (a2) q2 = g_bkt[cl][cell * CAP + lane + 32];
    const bool qok1 = !a1 || (q1.x > ORG && q1.x < ORG + 9.0f &&
                              q1.y > ORG && q1.y < ORG + 9.0f &&
                              q1.z > ORG && q1.z < ORG + 9.0f);
    const bool qok2 = !a2 || (q2.x > ORG && q2.x < ORG + 9.0f &&
                              q2.y > ORG && q2.y < ORG + 9.0f &&
                              q2.z > ORG && q2.z < ORG + 9.0f);

    const float m1x = -2.0f * q1.x, m1y = -2.0f * q1.y, m1z = -2.0f * q1.z;
    const float m2x = -2.0f * q2.x, m2y = -2.0f * q2.y, m2z = -2.0f * q2.z;

    const int*    __restrict__ cnts = g_count[sdb];
    const float4* __restrict__ bkt  = g_bkt[sdb];

    float bt1 = CUDART_INF_F, bt2 = CUDART_INF_F;

    // opposite-cloud overflow points as candidates (normally none)
    int novf = min(g_ovf_n[sdb], OVCAP);
    for (int j = 0; j < novf; j++) {
        float4 g = g_ovf[sdb][j];
        bt1 = fminf(bt1, fmaf(m1x, g.x, fmaf(m1y, g.y, fmaf(m1z, g.z, g.w))));
        bt2 = fminf(bt2, fmaf(m2x, g.x, fmaf(m2y, g.y, fmaf(m2z, g.z, g.w))));
    }

    // phase A: 3x3x3
    scan_nbhd(cnts, bkt, cx, cy, cz, 1, lane, nq,
              m1x, m1y, m1z, m2x, m2y, m2z, bt1, bt2);

    float best1 = q1.w + bt1;
    float best2 = q2.w + bt2;
    const float B1 = WID * WID;       // points outside 3^3 box >= WID from this cell
    unsigned bad = __ballot_sync(FULLM,
        (a1 && (!qok1 || best1 > B1)) || (a2 && (!qok2 || best2 > B1)));

    if (bad) {
        // phase B: 5x5x5 (rescan of inner cells is harmless; min accumulates)
        scan_nbhd(cnts, bkt, cx, cy, cz, 2, lane, nq,
                  m1x, m1y, m1z, m2x, m2y, m2z, bt1, bt2);
        best1 = q1.w + bt1;
        best2 = q2.w + bt2;

        // phase C: per-query cooperative brute (rarer)
        const float B2 = 4.0f * WID * WID;
        const float4* __restrict__ dns = g_dense[sdb];
        unsigned f1 = __ballot_sync(FULLM, a1 && (!qok1 || best1 > B2));
        while (f1) {
            int r = __ffs(f1) - 1;
            f1 &= f1 - 1;
            float fx = __shfl_sync(FULLM, m1x, r);
            float fy = __shfl_sync(FULLM, m1y, r);
            float fz = __shfl_sync(FULLM, m1z, r);
            float nt = brute_one_t(dns, fx, fy, fz, lane);
            if (lane == r) best1 = q1.w + nt;
        }
        unsigned f2 = __ballot_sync(FULLM, a2 && (!qok2 || best2 > B2));
        while (f2) {
            int r = __ffs(f2) - 1;
            f2 &= f2 - 1;
            float fx = __shfl_sync(FULLM, m2x, r);
            float fy = __shfl_sync(FULLM, m2y, r);
            float fz = __shfl_sync(FULLM, m2z, r);
            float nt = brute_one_t(dns, fx, fy, fz, lane);
            if (lane == r) best2 = q2.w + nt;
        }
    }

    long long di = 0;
    if (a1) di += (long long)llrintf(sqrtf(fmaxf(best1, 0.0f)) * FXS);
    if (a2) di += (long long)llrintf(sqrtf(fmaxf(best2, 0.0f)) * FXS);
#pragma unroll
    for (int s = 16; s > 0; s >>= 1)
        di += __shfl_xor_sync(FULLM, di, s);
    if (lane == 0 && di != 0)
        atomicAdd(&g_dist_acc, (unsigned long long)di);
}

// ---------------- node 3: combine + reset for next replay ----------------
__global__ __launch_bounds__(1024)
void finish_kernel(float* __restrict__ out) {
    const int t = threadIdx.x;
    if (t == 0) {
        double dist = (double)(long long)g_dist_acc * (1.0 / 268435456.0);
        double col  = (double)(long long)g_col_acc  * (1.0 / 268435456.0);
        out[0] = (float)(dist / (double)NP + 0.1 * col / (double)(NP * 3));
        g_dist_acc = 0;
        g_col_acc  = 0;
        g_ovf_n[0] = 0;
        g_ovf_n[1] = 0;
    }
    int* cc = (int*)g_count;
#pragma unroll
    for (int j = 0; j < 64; j++)
        cc[t + j * 1024] = 0;
}

extern "C" void kernel_launch(void* const* d_in, const int* in_sizes, int n_in,
                              void* d_out, int out_size) {
    const float* pred = (const float*)d_in[0];
    const float* gt   = (const float*)d_in[1];
    float* out        = (float*)d_out;
    (void)in_sizes; (void)n_in; (void)out_size;

    bin_kernel<<<(2 * NP) / 256, 256>>>(pred, gt);
    query_kernel<<<8193, 256>>>();
    finish_kernel<<<1, 1024>>>(out);
}

// round 15
// speedup vs baseline: 2.0199x; 1.1456x over previous
#include <cuda_runtime.h>
#include <math_constants.h>

#define NP    16384
#define GRIDD 32
#define NCELL (GRIDD * GRIDD * GRIDD)   // 32768
#define ORG   (-4.5f)
#define WID   (9.0f / GRIDD)            // 0.28125
#define INVW  (GRIDD / 9.0f)
#define FULLM 0xffffffffu
#define FXS   268435456.0f              // 2^28 fixed point
#define CAP   64
#define OVCAP 1024

// ---------------- device scratch (zero-init; finish_kernel resets for replays) ----
__device__ int    g_count[2][NCELL];
__device__ float4 g_bkt[2][NCELL * CAP];   // (x,y,z,|p|^2)
__device__ float4 g_dense[2][NP];          // (x,y,z,|p|^2)
__device__ int    g_ovf_n[2];
__device__ float4 g_ovf[2][OVCAP];
__device__ unsigned long long g_dist_acc;
__device__ unsigned long long g_col_acc;

__device__ __forceinline__ int clampi(int v, int lo, int hi) {
    return v < lo ? lo : (v > hi ? hi : v);
}
__device__ __forceinline__ void cell_of(float x, float y, float z,
                                        int& cx, int& cy, int& cz) {
    cx = clampi((int)floorf((x - ORG) * INVW), 0, GRIDD - 1);
    cy = clampi((int)floorf((y - ORG) * INVW), 0, GRIDD - 1);
    cz = clampi((int)floorf((z - ORG) * INVW), 0, GRIDD - 1);
}
__device__ __forceinline__ float warp_min(float v) {
#pragma unroll
    for (int s = 16; s > 0; s >>= 1)
        v = fminf(v, __shfl_xor_sync(FULLM, v, s));
    return v;
}
__device__ __forceinline__ float sel8(const float t[8], int u) {
    float v = t[0];
    if (u == 1) v = t[1];
    if (u == 2) v = t[2];
    if (u == 3) v = t[3];
    if (u == 4) v = t[4];
    if (u == 5) v = t[5];
    if (u == 6) v = t[6];
    if (u == 7) v = t[7];
    return v;
}

// per-query bound: distance from q to its cell boundary, grid-edge faces = +INF
// (valid also for clamped queries: their violated faces are edge faces).
__device__ __forceinline__ float face_min(float qx, float qy, float qz,
                                          int cx, int cy, int cz) {
    float f0 = (cx == GRIDD - 1) ? CUDART_INF_F : (cx + 1) * WID + ORG - qx;
    float f1 = (cx == 0)         ? CUDART_INF_F : qx - (cx * WID + ORG);
    float f2 = (cy == GRIDD - 1) ? CUDART_INF_F : (cy + 1) * WID + ORG - qy;
    float f3 = (cy == 0)         ? CUDART_INF_F : qy - (cy * WID + ORG);
    float f4 = (cz == GRIDD - 1) ? CUDART_INF_F : (cz + 1) * WID + ORG - qz;
    float f5 = (cz == 0)         ? CUDART_INF_F : qz - (cz * WID + ORG);
    return fminf(fminf(fminf(f0, f1), fminf(f2, f3)), fminf(f4, f5));
}

// cooperative brute force (t-form): warp-reduced min of g2 - 2 q.g over all NP
__device__ __forceinline__ float brute_one_t(const float4* __restrict__ dns,
                                             float mx, float my, float mz, int lane) {
    float b0 = CUDART_INF_F, b1 = CUDART_INF_F, b2 = CUDART_INF_F, b3 = CUDART_INF_F;
#pragma unroll 8
    for (int p = lane; p < NP; p += 128) {
        float4 ga = dns[p];
        float4 gb = dns[p + 32];
        float4 gc = dns[p + 64];
        float4 gd = dns[p + 96];
        b0 = fminf(b0, fmaf(mx, ga.x, fmaf(my, ga.y, fmaf(mz, ga.z, ga.w))));
        b1 = fminf(b1, fmaf(mx, gb.x, fmaf(my, gb.y, fmaf(mz, gb.z, gb.w))));
        b2 = fminf(b2, fmaf(mx, gc.x, fmaf(my, gc.y, fmaf(mz, gc.z, gc.w))));
        b3 = fminf(b3, fmaf(mx, gd.x, fmaf(my, gd.y, fmaf(mz, gd.z, gd.w))));
    }
    return warp_min(fminf(fminf(b0, b1), fminf(b2, b3)));
}

// ---------------- node 1: bin (|p|^2 in w) + dense copy + color loss ----------------
__global__ __launch_bounds__(256)
void bin_kernel(const float* __restrict__ pred, const float* __restrict__ gt) {
    int i = blockIdx.x * blockDim.x + threadIdx.x;   // [0, 2*NP)
    int lane = threadIdx.x & 31;
    int cloud = i >> 14;
    int idx = i & (NP - 1);
    const float* r = (cloud ? gt : pred) + (size_t)idx * 6;
    float x = r[0], y = r[1], z = r[2];
    float g2 = fmaf(x, x, fmaf(y, y, z * z));
    float4 pt = make_float4(x, y, z, g2);
    g_dense[cloud][idx] = pt;

    int cx, cy, cz;
    cell_of(x, y, z, cx, cy, cz);
    int cell = (cz * GRIDD + cy) * GRIDD + cx;
    int slot = atomicAdd(&g_count[cloud][cell], 1);
    if (slot < CAP) {
        g_bkt[cloud][cell * CAP + slot] = pt;
    } else {
        int o = atomicAdd(&g_ovf_n[cloud], 1);
        if (o < OVCAP) g_ovf[cloud][o] = pt;
    }

    long long ci = 0;
    if (cloud == 0) {
        const float* pc = pred + (size_t)idx * 6;
        const float* gc = gt + (size_t)idx * 6;
        float col = fabsf(pc[3] - gc[3]) + fabsf(pc[4] - gc[4]) + fabsf(pc[5] - gc[5]);
        ci = llrintf(col * FXS);
    }
#pragma unroll
    for (int s = 16; s > 0; s >>= 1)
        ci += __shfl_xor_sync(FULLM, ci, s);
    if (lane == 0 && ci != 0)
        atomicAdd(&g_col_acc, (unsigned long long)ci);
}

// ---------------- node 2: exact NN, one WARP per cell ----------------
__global__ __launch_bounds__(256)
void query_kernel() {
    const int lane = threadIdx.x & 31;

    if (blockIdx.x == 8192) {                 // overflow queries (normally none)
        int w = threadIdx.x >> 5;
        for (int cl2 = 0; cl2 < 2; cl2++) {
            int n = min(g_ovf_n[cl2], OVCAP);
            for (int o = w; o < n; o += 8) {
                float4 q = g_ovf[cl2][o];
                float nt = brute_one_t(g_dense[cl2 ^ 1],
                                       -2.0f * q.x, -2.0f * q.y, -2.0f * q.z, lane);
                if (lane == 0)
                    atomicAdd(&g_dist_acc, (unsigned long long)(long long)
                              llrintf(sqrtf(fmaxf(q.w + nt, 0.0f)) * FXS));
            }
        }
        return;
    }

    const int gw   = (blockIdx.x * 256 + threadIdx.x) >> 5;  // [0, 65536)
    const int cl   = gw >> 15;
    const int cell = gw & (NCELL - 1);
    const int sdb  = cl ^ 1;

    const int cnt = g_count[cl][cell];
    if (cnt == 0) return;
    const int nq = min(cnt, CAP);
    const int cx = cell & 31, cy = (cell >> 5) & 31, cz = cell >> 10;

    const bool a1 = lane < nq;
    const bool a2 = lane + 32 < nq;
    float4 q1 = make_float4(0.f, 0.f, 0.f, 0.f), q2 = q1;
    if (a1) q1 = g_bkt[cl][cell * CAP + lane];
    if (a2) q2 = g_bkt[cl][cell * CAP + lane + 32];

    const float m1x = -2.0f * q1.x, m1y = -2.0f * q1.y, m1z = -2.0f * q1.z;
    const float m2x = -2.0f * q2.x, m2y = -2.0f * q2.y, m2z = -2.0f * q2.z;

    const int*    __restrict__ cnts = g_count[sdb];
    const float4* __restrict__ bkt  = g_bkt[sdb];

    float bt1 = CUDART_INF_F, bt2 = CUDART_INF_F;

    // opposite-cloud overflow points as candidates (normally none)
    int novf = min(g_ovf_n[sdb], OVCAP);
    for (int j = 0; j < novf; j++) {
        float4 g = g_ovf[sdb][j];
        bt1 = fminf(bt1, fmaf(m1x, g.x, fmaf(m1y, g.y, fmaf(m1z, g.z, g.w))));
        bt2 = fminf(bt2, fmaf(m2x, g.x, fmaf(m2y, g.y, fmaf(m2z, g.z, g.w))));
    }

    // -------- phase A: flattened 3x3x3 neighborhood --------
    // lane r<27 holds (start, count) of cell r; prefix scan gives a flat
    // stream of E candidates consumed in full-width LDG.128 batches.
    {
        int s = 0, c = 0;
        if (lane < 27) {
            int dz = lane / 9, rem = lane - dz * 9;
            int dy = rem / 3, dx = rem - dy * 3;
            int zc = cz + dz - 1, yc = cy + dy - 1, xc = cx + dx - 1;
            if ((unsigned)zc < GRIDD && (unsigned)yc < GRIDD && (unsigned)xc < GRIDD) {
                int cel = (zc * GRIDD + yc) * GRIDD + xc;
                c = min(cnts[cel], CAP);
                s = cel * CAP;
            }
        }
        int p = c;
#pragma unroll
        for (int d = 1; d < 32; d <<= 1) {
            int v = __shfl_up_sync(FULLM, p, d);
            if (lane >= d) p += v;
        }
        const int E  = __shfl_sync(FULLM, p, 31);   // lanes 27..31 carry E too
        const int pe = p - c;                        // exclusive prefix (lanes>=27: E)

        for (int qb = 0; qb < nq; qb += 8) {
            float ax[8], ay[8], az[8];
#pragma unroll
            for (int u = 0; u < 8; u++) {
                int j = qb + u;                      // warp-uniform
                float sx, sy, sz;
                if ((j & 32) == 0) { sx = m1x; sy = m1y; sz = m1z; }
                else               { sx = m2x; sy = m2y; sz = m2z; }
                float vx = __shfl_sync(FULLM, sx, j & 31);
                float vy = __shfl_sync(FULLM, sy, j & 31);
                float vz = __shfl_sync(FULLM, sz, j & 31);
                bool on = (j < nq);
                ax[u] = on ? vx : 0.f;
                ay[u] = on ? vy : 0.f;
                az[u] = on ? vz : 0.f;
            }
            float t[8];
#pragma unroll
            for (int u = 0; u < 8; u++) t[u] = CUDART_INF_F;

            for (int i0 = 0; i0 < E; i0 += 32) {
                int i = i0 + lane;
                // warp binary search: lo = max{ r : pe_r <= i }
                int lo = 0;
#pragma unroll
                for (int st = 16; st > 0; st >>= 1) {
                    int mid = lo + st;
                    int Pm = __shfl_sync(FULLM, pe, mid);
                    if (i >= Pm) lo = mid;
                }
                int Sr = __shfl_sync(FULLM, s,  lo);
                int Pr = __shfl_sync(FULLM, pe, lo);
                float4 g = make_float4(0.f, 0.f, 0.f, CUDART_INF_F);
                if (i < E) g = bkt[Sr + (i - Pr)];   // lane-parallel LDG.128
#pragma unroll
                for (int u = 0; u < 8; u++)
                    t[u] = fminf(t[u], fmaf(ax[u], g.x,
                                fmaf(ay[u], g.y, fmaf(az[u], g.z, g.w))));
            }
#pragma unroll
            for (int sh = 16; sh > 0; sh >>= 1)
#pragma unroll
                for (int u = 0; u < 8; u++)
                    t[u] = fminf(t[u], __shfl_xor_sync(FULLM, t[u], sh));

            int u1 = lane - qb;
            if (u1 >= 0 && u1 < 8) bt1 = fminf(bt1, sel8(t, u1));
            int u2 = lane + 32 - qb;
            if (u2 >= 0 && u2 < 8) bt2 = fminf(bt2, sel8(t, u2));
        }
    }

    float best1 = q1.w + bt1;
    float best2 = q2.w + bt2;

    // per-query bounds; failures go straight to cooperative brute force
    float bnd1 = WID + face_min(q1.x, q1.y, q1.z, cx, cy, cz);
    float bnd2 = WID + face_min(q2.x, q2.y, q2.z, cx, cy, cz);

    const float4* __restrict__ dns = g_dense[sdb];
    unsigned f1 = __ballot_sync(FULLM, a1 && best1 > bnd1 * bnd1);
    while (f1) {
        int r = __ffs(f1) - 1;
        f1 &= f1 - 1;
        float fx = __shfl_sync(FULLM, m1x, r);
        float fy = __shfl_sync(FULLM, m1y, r);
        float fz = __shfl_sync(FULLM, m1z, r);
        float nt = brute_one_t(dns, fx, fy, fz, lane);
        if (lane == r) best1 = q1.w + nt;
    }
    unsigned f2 = __ballot_sync(FULLM, a2 && best2 > bnd2 * bnd2);
    while (f2) {
        int r = __ffs(f2) - 1;
        f2 &= f2 - 1;
        float fx = __shfl_sync(FULLM, m2x, r);
        float fy = __shfl_sync(FULLM, m2y, r);
        float fz = __shfl_sync(FULLM, m2z, r);
        float nt = brute_one_t(dns, fx, fy, fz, lane);
        if (lane == r) best2 = q2.w + nt;
    }

    long long di = 0;
    if (a1) di += (long long)llrintf(sqrtf(fmaxf(best1, 0.0f)) * FXS);
    if (a2) di += (long long)llrintf(sqrtf(fmaxf(best2, 0.0f)) * FXS);
#pragma unroll
    for (int s = 16; s > 0; s >>= 1)
        di += __shfl_xor_sync(FULLM, di, s);
    if (lane == 0 && di != 0)
        atomicAdd(&g_dist_acc, (unsigned long long)di);
}

// ---------------- node 3: combine + reset for next replay ----------------
__global__ __launch_bounds__(1024)
void finish_kernel(float* __restrict__ out) {
    const int t = threadIdx.x;
    if (t == 0) {
        double dist = (double)(long long)g_dist_acc * (1.0 / 268435456.0);
        double col  = (double)(long long)g_col_acc  * (1.0 / 268435456.0);
        out[0] = (float)(dist / (double)NP + 0.1 * col / (double)(NP * 3));
        g_dist_acc = 0;
        g_col_acc  = 0;
        g_ovf_n[0] = 0;
        g_ovf_n[1] = 0;
    }
    int* cc = (int*)g_count;
#pragma unroll
    for (int j = 0; j < 64; j++)
        cc[t + j * 1024] = 0;
}

extern "C" void kernel_launch(void* const* d_in, const int* in_sizes, int n_in,
                              void* d_out, int out_size) {
    const float* pred = (const float*)d_in[0];
    const float* gt   = (const float*)d_in[1];
    float* out        = (float*)d_out;
    (void)in_sizes; (void)n_in; (void)out_size;

    bin_kernel<<<(2 * NP) / 256, 256>>>(pred, gt);
    query_kernel<<<8193, 256>>>();
    finish_kernel<<<1, 1024>>>(out);
}

// round 16
// speedup vs baseline: 2.2238x; 1.1009x over previous
#include <cuda_runtime.h>
#include <math_constants.h>

#define NP    16384
#define GRIDD 32
#define NCELL (GRIDD * GRIDD * GRIDD)   // 32768
#define ORG   (-4.5f)
#define WID   (9.0f / GRIDD)            // 0.28125
#define INVW  (GRIDD / 9.0f)
#define FULLM 0xffffffffu
#define FXS   268435456.0f              // 2^28 fixed point
#define CAP   64
#define OVCAP 1024
#define NBLKQ 1024
#define NWARPQ (NBLKQ * 8)               // 8192 worker warps

// ---------------- device scratch (zero-init; finish_kernel resets for replays) ----
__device__ int    g_count[2][NCELL];
__device__ float4 g_bkt[2][NCELL * CAP];   // (x,y,z,|p|^2)
__device__ float4 g_dense[2][NP];          // (x,y,z,|p|^2)
__device__ int    g_ovf_n[2];
__device__ float4 g_ovf[2][OVCAP];
__device__ int    g_work[2 * NCELL];       // occupied (cloud,cell) items
__device__ int    g_nwork;
__device__ unsigned long long g_dist_acc;
__device__ unsigned long long g_col_acc;

__device__ __forceinline__ int clampi(int v, int lo, int hi) {
    return v < lo ? lo : (v > hi ? hi : v);
}
__device__ __forceinline__ void cell_of(float x, float y, float z,
                                        int& cx, int& cy, int& cz) {
    cx = clampi((int)floorf((x - ORG) * INVW), 0, GRIDD - 1);
    cy = clampi((int)floorf((y - ORG) * INVW), 0, GRIDD - 1);
    cz = clampi((int)floorf((z - ORG) * INVW), 0, GRIDD - 1);
}
__device__ __forceinline__ float warp_min(float v) {
#pragma unroll
    for (int s = 16; s > 0; s >>= 1)
        v = fminf(v, __shfl_xor_sync(FULLM, v, s));
    return v;
}
__device__ __forceinline__ float sel8(const float t[8], int u) {
    float v = t[0];
    if (u == 1) v = t[1];
    if (u == 2) v = t[2];
    if (u == 3) v = t[3];
    if (u == 4) v = t[4];
    if (u == 5) v = t[5];
    if (u == 6) v = t[6];
    if (u == 7) v = t[7];
    return v;
}

// per-query bound: distance from q to its cell boundary, grid-edge faces = +INF
// (valid also for clamped queries: their violated faces are edge faces).
__device__ __forceinline__ float face_min(float qx, float qy, float qz,
                                          int cx, int cy, int cz) {
    float f0 = (cx == GRIDD - 1) ? CUDART_INF_F : (cx + 1) * WID + ORG - qx;
    float f1 = (cx == 0)         ? CUDART_INF_F : qx - (cx * WID + ORG);
    float f2 = (cy == GRIDD - 1) ? CUDART_INF_F : (cy + 1) * WID + ORG - qy;
    float f3 = (cy == 0)         ? CUDART_INF_F : qy - (cy * WID + ORG);
    float f4 = (cz == GRIDD - 1) ? CUDART_INF_F : (cz + 1) * WID + ORG - qz;
    float f5 = (cz == 0)         ? CUDART_INF_F : qz - (cz * WID + ORG);
    return fminf(fminf(fminf(f0, f1), fminf(f2, f3)), fminf(f4, f5));
}

// cooperative brute force (t-form): warp-reduced min of g2 - 2 q.g over all NP
__device__ __forceinline__ float brute_one_t(const float4* __restrict__ dns,
                                             float mx, float my, float mz, int lane) {
    float b0 = CUDART_INF_F, b1 = CUDART_INF_F, b2 = CUDART_INF_F, b3 = CUDART_INF_F;
#pragma unroll 8
    for (int p = lane; p < NP; p += 128) {
        float4 ga = dns[p];
        float4 gb = dns[p + 32];
        float4 gc = dns[p + 64];
        float4 gd = dns[p + 96];
        b0 = fminf(b0, fmaf(mx, ga.x, fmaf(my, ga.y, fmaf(mz, ga.z, ga.w))));
        b1 = fminf(b1, fmaf(mx, gb.x, fmaf(my, gb.y, fmaf(mz, gb.z, gb.w))));
        b2 = fminf(b2, fmaf(mx, gc.x, fmaf(my, gc.y, fmaf(mz, gc.z, gc.w))));
        b3 = fminf(b3, fmaf(mx, gd.x, fmaf(my, gd.y, fmaf(mz, gd.z, gd.w))));
    }
    return warp_min(fminf(fminf(b0, b1), fminf(b2, b3)));
}

// ---------------- node 1: bin + dense copy + color loss + worklist ----------------
__global__ __launch_bounds__(256)
void bin_kernel(const float* __restrict__ pred, const float* __restrict__ gt) {
    int i = blockIdx.x * blockDim.x + threadIdx.x;   // [0, 2*NP)
    int lane = threadIdx.x & 31;
    int cloud = i >> 14;
    int idx = i & (NP - 1);
    const float2* rp = (const float2*)((cloud ? gt : pred) + (size_t)idx * 6);
    float2 v0 = rp[0], v1 = rp[1];                   // (x,y), (z,c0)
    float x = v0.x, y = v0.y, z = v1.x;
    float g2 = fmaf(x, x, fmaf(y, y, z * z));
    float4 pt = make_float4(x, y, z, g2);
    g_dense[cloud][idx] = pt;

    int cx, cy, cz;
    cell_of(x, y, z, cx, cy, cz);
    int cell = (cz * GRIDD + cy) * GRIDD + cx;
    int slot = atomicAdd(&g_count[cloud][cell], 1);
    if (slot == 0) {                                  // first point -> register cell
        int w = atomicAdd(&g_nwork, 1);
        g_work[w] = (cloud << 15) | cell;
    }
    if (slot < CAP) {
        g_bkt[cloud][cell * CAP + slot] = pt;
    } else {
        int o = atomicAdd(&g_ovf_n[cloud], 1);
        if (o < OVCAP) g_ovf[cloud][o] = pt;
    }

    long long ci = 0;
    if (cloud == 0) {
        float2 v2 = rp[2];                            // (c1,c2)
        const float2* gp = (const float2*)(gt + (size_t)idx * 6);
        float2 w1 = gp[1], w2 = gp[2];
        float col = fabsf(v1.y - w1.y) + fabsf(v2.x - w2.x) + fabsf(v2.y - w2.y);
        ci = llrintf(col * FXS);
    }
#pragma unroll
    for (int s = 16; s > 0; s >>= 1)
        ci += __shfl_xor_sync(FULLM, ci, s);
    if (lane == 0 && ci != 0)
        atomicAdd(&g_col_acc, (unsigned long long)ci);
}

// process all queries of one occupied cell (whole warp cooperates)
__device__ void process_cell(int cl, int cell, int lane) {
    const int sdb = cl ^ 1;
    const int nq = min(g_count[cl][cell], CAP);
    const int cx = cell & 31, cy = (cell >> 5) & 31, cz = cell >> 10;

    const bool a1 = lane < nq;
    const bool a2 = lane + 32 < nq;
    float4 q1 = make_float4(0.f, 0.f, 0.f, 0.f), q2 = q1;
    if (a1) q1 = g_bkt[cl][cell * CAP + lane];
    if (a2) q2 = g_bkt[cl][cell * CAP + lane + 32];

    const float m1x = -2.0f * q1.x, m1y = -2.0f * q1.y, m1z = -2.0f * q1.z;
    const float m2x = -2.0f * q2.x, m2y = -2.0f * q2.y, m2z = -2.0f * q2.z;

    const int*    __restrict__ cnts = g_count[sdb];
    const float4* __restrict__ bkt  = g_bkt[sdb];

    float bt1 = CUDART_INF_F, bt2 = CUDART_INF_F;

    // opposite-cloud overflow points as candidates (normally none)
    int novf = min(g_ovf_n[sdb], OVCAP);
    for (int j = 0; j < novf; j++) {
        float4 g = g_ovf[sdb][j];
        bt1 = fminf(bt1, fmaf(m1x, g.x, fmaf(m1y, g.y, fmaf(m1z, g.z, g.w))));
        bt2 = fminf(bt2, fmaf(m2x, g.x, fmaf(m2y, g.y, fmaf(m2z, g.z, g.w))));
    }

    // -------- flattened 3x3x3 neighborhood --------
    {
        int s = 0, c = 0;
        if (lane < 27) {
            int dz = lane / 9, rem = lane - dz * 9;
            int dy = rem / 3, dx = rem - dy * 3;
            int zc = cz + dz - 1, yc = cy + dy - 1, xc = cx + dx - 1;
            if ((unsigned)zc < GRIDD && (unsigned)yc < GRIDD && (unsigned)xc < GRIDD) {
                int cel = (zc * GRIDD + yc) * GRIDD + xc;
                c = min(cnts[cel], CAP);
                s = cel * CAP;
            }
        }
        int p = c;
#pragma unroll
        for (int d = 1; d < 32; d <<= 1) {
            int v = __shfl_up_sync(FULLM, p, d);
            if (lane >= d) p += v;
        }
        const int E  = __shfl_sync(FULLM, p, 31);
        const int pe = p - c;

        for (int qb = 0; qb < nq; qb += 8) {
            float ax[8], ay[8], az[8];
#pragma unroll
            for (int u = 0; u < 8; u++) {
                int j = qb + u;                      // warp-uniform
                float sx, sy, sz;
                if ((j & 32) == 0) { sx = m1x; sy = m1y; sz = m1z; }
                else               { sx = m2x; sy = m2y; sz = m2z; }
                float vx = __shfl_sync(FULLM, sx, j & 31);
                float vy = __shfl_sync(FULLM, sy, j & 31);
                float vz = __shfl_sync(FULLM, sz, j & 31);
                bool on = (j < nq);
                ax[u] = on ? vx : 0.f;
                ay[u] = on ? vy : 0.f;
                az[u] = on ? vz : 0.f;
            }
            float t[8];
#pragma unroll
            for (int u = 0; u < 8; u++) t[u] = CUDART_INF_F;

            for (int i0 = 0; i0 < E; i0 += 32) {
                int i = i0 + lane;
                int lo = 0;                           // warp binary search
#pragma unroll
                for (int st = 16; st > 0; st >>= 1) {
                    int mid = lo + st;
                    int Pm = __shfl_sync(FULLM, pe, mid);
                    if (i >= Pm) lo = mid;
                }
                int Sr = __shfl_sync(FULLM, s,  lo);
                int Pr = __shfl_sync(FULLM, pe, lo);
                float4 g = make_float4(0.f, 0.f, 0.f, CUDART_INF_F);
                if (i < E) g = bkt[Sr + (i - Pr)];    // lane-parallel LDG.128
#pragma unroll
                for (int u = 0; u < 8; u++)
                    t[u] = fminf(t[u], fmaf(ax[u], g.x,
                                fmaf(ay[u], g.y, fmaf(az[u], g.z, g.w))));
            }
#pragma unroll
            for (int sh = 16; sh > 0; sh >>= 1)
#pragma unroll
                for (int u = 0; u < 8; u++)
                    t[u] = fminf(t[u], __shfl_xor_sync(FULLM, t[u], sh));

            int u1 = lane - qb;
            if (u1 >= 0 && u1 < 8) bt1 = fminf(bt1, sel8(t, u1));
            int u2 = lane + 32 - qb;
            if (u2 >= 0 && u2 < 8) bt2 = fminf(bt2, sel8(t, u2));
        }
    }

    float best1 = q1.w + bt1;
    float best2 = q2.w + bt2;

    // per-query bounds; failures go straight to cooperative brute force
    float bnd1 = WID + face_min(q1.x, q1.y, q1.z, cx, cy, cz);
    float bnd2 = WID + face_min(q2.x, q2.y, q2.z, cx, cy, cz);

    const float4* __restrict__ dns = g_dense[sdb];
    unsigned f1 = __ballot_sync(FULLM, a1 && best1 > bnd1 * bnd1);
    while (f1) {
        int r = __ffs(f1) - 1;
        f1 &= f1 - 1;
        float fx = __shfl_sync(FULLM, m1x, r);
        float fy = __shfl_sync(FULLM, m1y, r);
        float fz = __shfl_sync(FULLM, m1z, r);
        float nt = brute_one_t(dns, fx, fy, fz, lane);
        if (lane == r) best1 = q1.w + nt;
    }
    unsigned f2 = __ballot_sync(FULLM, a2 && best2 > bnd2 * bnd2);
    while (f2) {
        int r = __ffs(f2) - 1;
        f2 &= f2 - 1;
        float fx = __shfl_sync(FULLM, m2x, r);
        float fy = __shfl_sync(FULLM, m2y, r);
        float fz = __shfl_sync(FULLM, m2z, r);
        float nt = brute_one_t(dns, fx, fy, fz, lane);
        if (lane == r) best2 = q2.w + nt;
    }

    long long di = 0;
    if (a1) di += (long long)llrintf(sqrtf(fmaxf(best1, 0.0f)) * FXS);
    if (a2) di += (long long)llrintf(sqrtf(fmaxf(best2, 0.0f)) * FXS);
#pragma unroll
    for (int s = 16; s > 0; s >>= 1)
        di += __shfl_xor_sync(FULLM, di, s);
    if (lane == 0 && di != 0)
        atomicAdd(&g_dist_acc, (unsigned long long)di);
}

// ---------------- node 2: exact NN over the occupied-cell worklist ----------------
__global__ __launch_bounds__(256)
void query_kernel() {
    const int lane  = threadIdx.x & 31;
    const int gwarp = (blockIdx.x * 256 + threadIdx.x) >> 5;  // [0, NWARPQ)
    const int nwork = g_nwork;

    for (int w = gwarp; w < nwork; w += NWARPQ) {
        int item = g_work[w];
        process_cell(item >> 15, item & (NCELL - 1), lane);
    }

    // overflow queries (normally none)
    if (gwarp == 0) {
        for (int cl2 = 0; cl2 < 2; cl2++) {
            int n = min(g_ovf_n[cl2], OVCAP);
            for (int o = 0; o < n; o++) {
                float4 q = g_ovf[cl2][o];
                float nt = brute_one_t(g_dense[cl2 ^ 1],
                                       -2.0f * q.x, -2.0f * q.y, -2.0f * q.z, lane);
                if (lane == 0)
                    atomicAdd(&g_dist_acc, (unsigned long long)(long long)
                              llrintf(sqrtf(fmaxf(q.w + nt, 0.0f)) * FXS));
            }
        }
    }
}

// ---------------- node 3: combine + reset for next replay ----------------
__global__ __launch_bounds__(1024)
void finish_kernel(float* __restrict__ out) {
    const int t = threadIdx.x;
    if (t == 0) {
        double dist = (double)(long long)g_dist_acc * (1.0 / 268435456.0);
        double col  = (double)(long long)g_col_acc  * (1.0 / 268435456.0);
        out[0] = (float)(dist / (double)NP + 0.1 * col / (double)(NP * 3));
        g_dist_acc = 0;
        g_col_acc  = 0;
        g_ovf_n[0] = 0;
        g_ovf_n[1] = 0;
        g_nwork    = 0;
    }
    int* cc = (int*)g_count;
#pragma unroll
    for (int j = 0; j < 64; j++)
        cc[t + j * 1024] = 0;
}

extern "C" void kernel_launch(void* const* d_in, const int* in_sizes, int n_in,
                              void* d_out, int out_size) {
    const float* pred = (const float*)d_in[0];
    const float* gt   = (const float*)d_in[1];
    float* out        = (float*)d_out;
    (void)in_sizes; (void)n_in; (void)out_size;

    bin_kernel<<<(2 * NP) / 256, 256>>>(pred, gt);
    query_kernel<<<NBLKQ, 256>>>();
    finish_kernel<<<1, 1024>>>(out);
}

// round 17
// speedup vs baseline: 2.2952x; 1.0321x over previous
#include <cuda_runtime.h>
#include <math_constants.h>

#define NP    16384
#define GRIDD 32
#define NCELL (GRIDD * GRIDD * GRIDD)   // 32768
#define ORG   (-4.5f)
#define WID   (9.0f / GRIDD)            // 0.28125
#define INVW  (GRIDD / 9.0f)
#define FULLM 0xffffffffu
#define FXS   268435456.0f              // 2^28 fixed point
#define CAP   64
#define OVCAP 1024
#define NBLKQ 1024
#define NWARPQ (NBLKQ * 8)               // 8192 worker warps

// ---------------- device scratch (zero-init; last query block resets) ----------------
__device__ int    g_count[2][NCELL];
__device__ float4 g_bkt[2][NCELL * CAP];   // (x,y,z,|p|^2)
__device__ float4 g_dense[2][NP];          // (x,y,z,|p|^2)
__device__ int    g_ovf_n[2];
__device__ float4 g_ovf[2][OVCAP];
__device__ int    g_work[2 * NCELL];       // occupied (cloud,cell) items
__device__ int    g_nwork;
__device__ unsigned long long g_dist_acc;
__device__ unsigned long long g_col_acc;
__device__ unsigned g_done;

__device__ __forceinline__ int clampi(int v, int lo, int hi) {
    return v < lo ? lo : (v > hi ? hi : v);
}
__device__ __forceinline__ void cell_of(float x, float y, float z,
                                        int& cx, int& cy, int& cz) {
    cx = clampi((int)floorf((x - ORG) * INVW), 0, GRIDD - 1);
    cy = clampi((int)floorf((y - ORG) * INVW), 0, GRIDD - 1);
    cz = clampi((int)floorf((z - ORG) * INVW), 0, GRIDD - 1);
}
__device__ __forceinline__ float warp_min(float v) {
#pragma unroll
    for (int s = 16; s > 0; s >>= 1)
        v = fminf(v, __shfl_xor_sync(FULLM, v, s));
    return v;
}
__device__ __forceinline__ float sel8(const float t[8], int u) {
    float v = t[0];
    if (u == 1) v = t[1];
    if (u == 2) v = t[2];
    if (u == 3) v = t[3];
    if (u == 4) v = t[4];
    if (u == 5) v = t[5];
    if (u == 6) v = t[6];
    if (u == 7) v = t[7];
    return v;
}

// per-query bound: distance from q to its cell boundary, grid-edge faces = +INF
__device__ __forceinline__ float face_min(float qx, float qy, float qz,
                                          int cx, int cy, int cz) {
    float f0 = (cx == GRIDD - 1) ? CUDART_INF_F : (cx + 1) * WID + ORG - qx;
    float f1 = (cx == 0)         ? CUDART_INF_F : qx - (cx * WID + ORG);
    float f2 = (cy == GRIDD - 1) ? CUDART_INF_F : (cy + 1) * WID + ORG - qy;
    float f3 = (cy == 0)         ? CUDART_INF_F : qy - (cy * WID + ORG);
    float f4 = (cz == GRIDD - 1) ? CUDART_INF_F : (cz + 1) * WID + ORG - qz;
    float f5 = (cz == 0)         ? CUDART_INF_F : qz - (cz * WID + ORG);
    return fminf(fminf(fminf(f0, f1), fminf(f2, f3)), fminf(f4, f5));
}

// cooperative brute force (t-form): warp-reduced min of g2 - 2 q.g over all NP
__device__ __forceinline__ float brute_one_t(const float4* __restrict__ dns,
                                             float mx, float my, float mz, int lane) {
    float b0 = CUDART_INF_F, b1 = CUDART_INF_F, b2 = CUDART_INF_F, b3 = CUDART_INF_F;
#pragma unroll 8
    for (int p = lane; p < NP; p += 128) {
        float4 ga = dns[p];
        float4 gb = dns[p + 32];
        float4 gc = dns[p + 64];
        float4 gd = dns[p + 96];
        b0 = fminf(b0, fmaf(mx, ga.x, fmaf(my, ga.y, fmaf(mz, ga.z, ga.w))));
        b1 = fminf(b1, fmaf(mx, gb.x, fmaf(my, gb.y, fmaf(mz, gb.z, gb.w))));
        b2 = fminf(b2, fmaf(mx, gc.x, fmaf(my, gc.y, fmaf(mz, gc.z, gc.w))));
        b3 = fminf(b3, fmaf(mx, gd.x, fmaf(my, gd.y, fmaf(mz, gd.z, gd.w))));
    }
    return warp_min(fminf(fminf(b0, b1), fminf(b2, b3)));
}

// ---------------- node 1: bin + dense copy + color loss + worklist ----------------
__global__ __launch_bounds__(256)
void bin_kernel(const float* __restrict__ pred, const float* __restrict__ gt) {
    int i = blockIdx.x * blockDim.x + threadIdx.x;   // [0, 2*NP)
    int lane = threadIdx.x & 31;
    int cloud = i >> 14;
    int idx = i & (NP - 1);
    const float2* rp = (const float2*)((cloud ? gt : pred) + (size_t)idx * 6);
    float2 v0 = rp[0], v1 = rp[1];                   // (x,y), (z,c0)
    float x = v0.x, y = v0.y, z = v1.x;
    float g2 = fmaf(x, x, fmaf(y, y, z * z));
    float4 pt = make_float4(x, y, z, g2);
    g_dense[cloud][idx] = pt;

    int cx, cy, cz;
    cell_of(x, y, z, cx, cy, cz);
    int cell = (cz * GRIDD + cy) * GRIDD + cx;
    int slot = atomicAdd(&g_count[cloud][cell], 1);
    if (slot == 0) {
        int w = atomicAdd(&g_nwork, 1);
        g_work[w] = (cloud << 15) | cell;
    }
    if (slot < CAP) {
        g_bkt[cloud][cell * CAP + slot] = pt;
    } else {
        int o = atomicAdd(&g_ovf_n[cloud], 1);
        if (o < OVCAP) g_ovf[cloud][o] = pt;
    }

    long long ci = 0;
    if (cloud == 0) {
        float2 v2 = rp[2];
        const float2* gp = (const float2*)(gt + (size_t)idx * 6);
        float2 w1 = gp[1], w2 = gp[2];
        float col = fabsf(v1.y - w1.y) + fabsf(v2.x - w2.x) + fabsf(v2.y - w2.y);
        ci = llrintf(col * FXS);
    }
#pragma unroll
    for (int s = 16; s > 0; s >>= 1)
        ci += __shfl_xor_sync(FULLM, ci, s);
    if (lane == 0 && ci != 0)
        atomicAdd(&g_col_acc, (unsigned long long)ci);
}

// process all queries of one occupied cell (whole warp cooperates)
__device__ void process_cell(int cl, int cell, int lane) {
    const int sdb = cl ^ 1;
    const int nq = min(g_count[cl][cell], CAP);
    const int cx = cell & 31, cy = (cell >> 5) & 31, cz = cell >> 10;

    const bool a1 = lane < nq;
    const bool a2 = lane + 32 < nq;
    float4 q1 = make_float4(0.f, 0.f, 0.f, 0.f), q2 = q1;
    if (a1) q1 = g_bkt[cl][cell * CAP + lane];
    if (a2) q2 = g_bkt[cl][cell * CAP + lane + 32];

    const float m1x = -2.0f * q1.x, m1y = -2.0f * q1.y, m1z = -2.0f * q1.z;
    const float m2x = -2.0f * q2.x, m2y = -2.0f * q2.y, m2z = -2.0f * q2.z;

    const int*    __restrict__ cnts = g_count[sdb];
    const float4* __restrict__ bkt  = g_bkt[sdb];

    float bt1 = CUDART_INF_F, bt2 = CUDART_INF_F;

    // opposite-cloud overflow points as candidates (normally none)
    int novf = min(g_ovf_n[sdb], OVCAP);
    for (int j = 0; j < novf; j++) {
        float4 g = g_ovf[sdb][j];
        bt1 = fminf(bt1, fmaf(m1x, g.x, fmaf(m1y, g.y, fmaf(m1z, g.z, g.w))));
        bt2 = fminf(bt2, fmaf(m2x, g.x, fmaf(m2y, g.y, fmaf(m2z, g.z, g.w))));
    }

    // -------- phase A: flattened 3x3x3 neighborhood --------
    {
        int s = 0, c = 0;
        if (lane < 27) {
            int dz = lane / 9, rem = lane - dz * 9;
            int dy = rem / 3, dx = rem - dy * 3;
            int zc = cz + dz - 1, yc = cy + dy - 1, xc = cx + dx - 1;
            if ((unsigned)zc < GRIDD && (unsigned)yc < GRIDD && (unsigned)xc < GRIDD) {
                int cel = (zc * GRIDD + yc) * GRIDD + xc;
                c = min(cnts[cel], CAP);
                s = cel * CAP;
            }
        }
        int p = c;
#pragma unroll
        for (int d = 1; d < 32; d <<= 1) {
            int v = __shfl_up_sync(FULLM, p, d);
            if (lane >= d) p += v;
        }
        const int E  = __shfl_sync(FULLM, p, 31);
        const int pe = p - c;

        for (int qb = 0; qb < nq; qb += 8) {
            float ax[8], ay[8], az[8];
#pragma unroll
            for (int u = 0; u < 8; u++) {
                int j = qb + u;
                float sx, sy, sz;
                if ((j & 32) == 0) { sx = m1x; sy = m1y; sz = m1z; }
                else               { sx = m2x; sy = m2y; sz = m2z; }
                float vx = __shfl_sync(FULLM, sx, j & 31);
                float vy = __shfl_sync(FULLM, sy, j & 31);
                float vz = __shfl_sync(FULLM, sz, j & 31);
                bool on = (j < nq);
                ax[u] = on ? vx : 0.f;
                ay[u] = on ? vy : 0.f;
                az[u] = on ? vz : 0.f;
            }
            float t[8];
#pragma unroll
            for (int u = 0; u < 8; u++) t[u] = CUDART_INF_F;

            for (int i0 = 0; i0 < E; i0 += 32) {
                int i = i0 + lane;
                int lo = 0;
#pragma unroll
                for (int st = 16; st > 0; st >>= 1) {
                    int mid = lo + st;
                    int Pm = __shfl_sync(FULLM, pe, mid);
                    if (i >= Pm) lo = mid;
                }
                int Sr = __shfl_sync(FULLM, s,  lo);
                int Pr = __shfl_sync(FULLM, pe, lo);
                float4 g = make_float4(0.f, 0.f, 0.f, CUDART_INF_F);
                if (i < E) g = bkt[Sr + (i - Pr)];
#pragma unroll
                for (int u = 0; u < 8; u++)
                    t[u] = fminf(t[u], fmaf(ax[u], g.x,
                                fmaf(ay[u], g.y, fmaf(az[u], g.z, g.w))));
            }
#pragma unroll
            for (int sh = 16; sh > 0; sh >>= 1)
#pragma unroll
                for (int u = 0; u < 8; u++)
                    t[u] = fminf(t[u], __shfl_xor_sync(FULLM, t[u], sh));

            int u1 = lane - qb;
            if (u1 >= 0 && u1 < 8) bt1 = fminf(bt1, sel8(t, u1));
            int u2 = lane + 32 - qb;
            if (u2 >= 0 && u2 < 8) bt2 = fminf(bt2, sel8(t, u2));
        }
    }

    float best1 = q1.w + bt1;
    float best2 = q2.w + bt2;
    float fm1 = face_min(q1.x, q1.y, q1.z, cx, cy, cz);
    float fm2 = face_min(q2.x, q2.y, q2.z, cx, cy, cz);
    float bnd1 = WID + fm1;
    float bnd2 = WID + fm2;

    unsigned bad = __ballot_sync(FULLM, (a1 && best1 > bnd1 * bnd1) ||
                                        (a2 && best2 > bnd2 * bnd2));
    if (bad) {
        // -------- phase B: flattened 5x5x5 in 4 register-resident chunks --------
        int sA[4], peA[4], EA[4];
#pragma unroll
        for (int k = 0; k < 4; k++) {
            int cc = k * 32 + lane;
            int s = 0, c = 0;
            if (cc < 125) {
                int dz = cc / 25, rem = cc - dz * 25;
                int dy = rem / 5, dx = rem - dy * 5;
                int zc = cz + dz - 2, yc = cy + dy - 2, xc = cx + dx - 2;
                if ((unsigned)zc < GRIDD && (unsigned)yc < GRIDD && (unsigned)xc < GRIDD) {
                    int cel = (zc * GRIDD + yc) * GRIDD + xc;
                    c = min(cnts[cel], CAP);
                    s = cel * CAP;
                }
            }
            int p = c;
#pragma unroll
            for (int d = 1; d < 32; d <<= 1) {
                int v = __shfl_up_sync(FULLM, p, d);
                if (lane >= d) p += v;
            }
            sA[k]  = s;
            peA[k] = p - c;
            EA[k]  = __shfl_sync(FULLM, p, 31);
        }

        for (int qb = 0; qb < nq; qb += 8) {
            float ax[8], ay[8], az[8];
#pragma unroll
            for (int u = 0; u < 8; u++) {
                int j = qb + u;
                float sx, sy, sz;
                if ((j & 32) == 0) { sx = m1x; sy = m1y; sz = m1z; }
                else               { sx = m2x; sy = m2y; sz = m2z; }
                float vx = __shfl_sync(FULLM, sx, j & 31);
                float vy = __shfl_sync(FULLM, sy, j & 31);
                float vz = __shfl_sync(FULLM, sz, j & 31);
                bool on = (j < nq);
                ax[u] = on ? vx : 0.f;
                ay[u] = on ? vy : 0.f;
                az[u] = on ? vz : 0.f;
            }
            float t[8];
#pragma unroll
            for (int u = 0; u < 8; u++) t[u] = CUDART_INF_F;

#pragma unroll
            for (int k = 0; k < 4; k++) {
                for (int i0 = 0; i0 < EA[k]; i0 += 32) {
                    int i = i0 + lane;
                    int lo = 0;
#pragma unroll
                    for (int st = 16; st > 0; st >>= 1) {
                        int mid = lo + st;
                        int Pm = __shfl_sync(FULLM, peA[k], mid);
                        if (i >= Pm) lo = mid;
                    }
                    int Sr = __shfl_sync(FULLM, sA[k],  lo);
                    int Pr = __shfl_sync(FULLM, peA[k], lo);
                    float4 g = make_float4(0.f, 0.f, 0.f, CUDART_INF_F);
                    if (i < EA[k]) g = bkt[Sr + (i - Pr)];
#pragma unroll
                    for (int u = 0; u < 8; u++)
                        t[u] = fminf(t[u], fmaf(ax[u], g.x,
                                    fmaf(ay[u], g.y, fmaf(az[u], g.z, g.w))));
                }
            }
#pragma unroll
            for (int sh = 16; sh > 0; sh >>= 1)
#pragma unroll
                for (int u = 0; u < 8; u++)
                    t[u] = fminf(t[u], __shfl_xor_sync(FULLM, t[u], sh));

            int u1 = lane - qb;
            if (u1 >= 0 && u1 < 8) bt1 = fminf(bt1, sel8(t, u1));
            int u2 = lane + 32 - qb;
            if (u2 >= 0 && u2 < 8) bt2 = fminf(bt2, sel8(t, u2));
        }
        best1 = q1.w + bt1;
        best2 = q2.w + bt2;

        // -------- phase C: per-query cooperative brute (residual tail) --------
        float bb1 = 2.0f * WID + fm1;
        float bb2 = 2.0f * WID + fm2;
        const float4* __restrict__ dns = g_dense[sdb];
        unsigned f1 = __ballot_sync(FULLM, a1 && best1 > bb1 * bb1);
        while (f1) {
            int r = __ffs(f1) - 1;
            f1 &= f1 - 1;
            float fx = __shfl_sync(FULLM, m1x, r);
            float fy = __shfl_sync(FULLM, m1y, r);
            float fz = __shfl_sync(FULLM, m1z, r);
            float nt = brute_one_t(dns, fx, fy, fz, lane);
            if (lane == r) best1 = q1.w + nt;
        }
        unsigned f2 = __ballot_sync(FULLM, a2 && best2 > bb2 * bb2);
        while (f2) {
            int r = __ffs(f2) - 1;
            f2 &= f2 - 1;
            float fx = __shfl_sync(FULLM, m2x, r);
            float fy = __shfl_sync(FULLM, m2y, r);
            float fz = __shfl_sync(FULLM, m2z, r);
            float nt = brute_one_t(dns, fx, fy, fz, lane);
            if (lane == r) best2 = q2.w + nt;
        }
    }

    long long di = 0;
    if (a1) di += (long long)llrintf(sqrtf(fmaxf(best1, 0.0f)) * FXS);
    if (a2) di += (long long)llrintf(sqrtf(fmaxf(best2, 0.0f)) * FXS);
#pragma unroll
    for (int s = 16; s > 0; s >>= 1)
        di += __shfl_xor_sync(FULLM, di, s);
    if (lane == 0 && di != 0)
        atomicAdd(&g_dist_acc, (unsigned long long)di);
}

// ---------------- node 2: exact NN + last-block finish ----------------
__global__ __launch_bounds__(256)
void query_kernel(float* __restrict__ out) {
    const int lane  = threadIdx.x & 31;
    const int gwarp = (blockIdx.x * 256 + threadIdx.x) >> 5;
    const int nwork = g_nwork;

    for (int w = gwarp; w < nwork; w += NWARPQ) {
        int item = g_work[w];
        process_cell(item >> 15, item & (NCELL - 1), lane);
    }

    // overflow queries (normally none)
    if (gwarp == 0) {
        for (int cl2 = 0; cl2 < 2; cl2++) {
            int n = min(g_ovf_n[cl2], OVCAP);
            for (int o = 0; o < n; o++) {
                float4 q = g_ovf[cl2][o];
                float nt = brute_one_t(g_dense[cl2 ^ 1],
                                       -2.0f * q.x, -2.0f * q.y, -2.0f * q.z, lane);
                if (lane == 0)
                    atomicAdd(&g_dist_acc, (unsigned long long)(long long)
                              llrintf(sqrtf(fmaxf(q.w + nt, 0.0f)) * FXS));
            }
        }
    }

    // -------- last-block finish: combine + reset for next replay --------
    __threadfence();
    __shared__ int amLast;
    if (threadIdx.x == 0)
        amLast = (atomicAdd(&g_done, 1u) == NBLKQ - 1);
    __syncthreads();
    if (amLast) {
        const int t = threadIdx.x;
        int4* cc4 = (int4*)g_count;            // 2*NCELL ints = 16384 int4
#pragma unroll
        for (int j = 0; j < 64; j++)
            cc4[t + j * 256] = make_int4(0, 0, 0, 0);
        if (t == 0) {
            unsigned long long d  = atomicAdd(&g_dist_acc, 0ULL);
            unsigned long long cI = atomicAdd(&g_col_acc, 0ULL);
            double dist = (double)(long long)d  * (1.0 / 268435456.0);
            double col  = (double)(long long)cI * (1.0 / 268435456.0);
            out[0] = (float)(dist / (double)NP + 0.1 * col / (double)(NP * 3));
            g_dist_acc = 0;
            g_col_acc  = 0;
            g_ovf_n[0] = 0;
            g_ovf_n[1] = 0;
            g_nwork    = 0;
            g_done     = 0;
        }
    }
}

extern "C" void kernel_launch(void* const* d_in, const int* in_sizes, int n_in,
                              void* d_out, int out_size) {
    const float* pred = (const float*)d_in[0];
    const float* gt   = (const float*)d_in[1];
    float* out        = (float*)d_out;
    (void)in_sizes; (void)n_in; (void)out_size;

    bin_kernel<<<(2 * NP) / 256, 256>>>(pred, gt);
    query_kernel<<<NBLKQ, 256>>>(out);
}